// round 15
// baseline (speedup 1.0000x reference)
#include <cuda_runtime.h>
#include <cuda_bf16.h>
#include <math.h>
#include <stdint.h>

#define NM 100000
#define ND 20000
#define NA 50000
#define NSRC (ND + NA)
#define NE 300000
#define EE (2 * NE)
#define HID 128

// ---------------- scratch ----------------
__device__ float d_xs0[NM * HID];
__device__ float d_q0[NM * HID];
__device__ float d_ktmt[(size_t)NSRC * 256];   // per-src: cols 0-127 = K, 128-255 = M
__device__ int   d_cnt[NM];
__device__ int   d_rowptr[NM];
__device__ int   d_cursor[NM];
__device__ int   d_col[EE];
__device__ int   d_scanIncl[128];
__device__ int   d_scanFlag[128];
__device__ float d_binK[2][HID];
__device__ float d_binM[2][HID];
__device__ float d_tmpK[2][HID * HID];
__device__ float d_tmpM[2][HID * HID];
__device__ float d_WKM[2][HID * 256];
__device__ float d_bKM[2][256];
__device__ float d_W1[HID * 8];
__device__ float d_W2[HID * 8];
__device__ float d_bf[8];

// ---------------- CSR: count + fill ----------------
__global__ void k_count(const int* __restrict__ dst_dm, const int* __restrict__ dst_am) {
    int i = blockIdx.x * blockDim.x + threadIdx.x;
    if (i < NE)       atomicAdd(&d_cnt[dst_dm[i]], 1);
    else if (i < EE)  atomicAdd(&d_cnt[dst_am[i - NE]], 1);
}

__global__ void k_fill(const int* __restrict__ src_dm, const int* __restrict__ dst_dm,
                       const int* __restrict__ src_am, const int* __restrict__ dst_am) {
    int i = blockIdx.x * blockDim.x + threadIdx.x;
    if (i >= EE) return;
    int dst, src;
    if (i < NE) { dst = dst_dm[i]; src = src_dm[i]; }
    else        { dst = dst_am[i - NE]; src = ND + src_am[i - NE]; }
    int pos = atomicAdd(&d_cursor[dst], 1);
    d_col[pos] = src;
}

// ---------------- single-pass scan with chained lookback (98 blocks, all resident) ----
__global__ void k_scan(int nblk) {
    __shared__ int s[1024];
    __shared__ int s_prev;
    int b = blockIdx.x, tid = threadIdx.x;
    int idx = b * 1024 + tid;
    int v = (idx < NM) ? d_cnt[idx] : 0;
    s[tid] = v;
    __syncthreads();
    #pragma unroll
    for (int off = 1; off < 1024; off <<= 1) {
        int t = (tid >= off) ? s[tid - off] : 0;
        __syncthreads();
        s[tid] += t;
        __syncthreads();
    }
    if (tid == 0) {
        int prev = 0;
        if (b > 0) {
            while (atomicAdd(&d_scanFlag[b - 1], 0) == 0) { }
            prev = atomicAdd(&d_scanIncl[b - 1], 0);
        }
        atomicExch(&d_scanIncl[b], prev + s[1023]);
        __threadfence();
        atomicExch(&d_scanFlag[b], 1);
        s_prev = prev;
    }
    __syncthreads();
    if (idx < NM) {
        int r = s_prev + s[tid] - v;     // exclusive prefix
        d_rowptr[idx] = r;
        d_cursor[idx] = r;
    }
}

// ---------------- fused weight prep (phase 1): compose + bias_inner + head ----------------
__global__ void k_prep1(const float* __restrict__ bpre,
                        const float* __restrict__ Wk, const float* __restrict__ bk,
                        const float* __restrict__ Wv, const float* __restrict__ bv,
                        const float* __restrict__ a_rel, const float* __restrict__ m_rel,
                        const float* __restrict__ p_rel,
                        const float* __restrict__ Wa, const float* __restrict__ ba,
                        const float* __restrict__ Wlin, const float* __restrict__ blin,
                        const float* __restrict__ skip) {
    int blk = blockIdx.x;
    int tid = threadIdx.x;
    if (blk < 256) {
        int idx = blk * 256 + tid;
        int mat = idx >> 14;
        int rem = idx & 16383;
        int i = rem >> 7;
        int o = rem & 127;
        int h = o >> 4, f = o & 15;
        int t = mat >> 1;
        bool isK = (mat & 1) == 0;
        int st = t + 1;
        const float* W = isK ? Wk : Wv;
        const float* R = isK ? a_rel : m_rel;
        const float* w = W + st * HID * HID + i * HID + h * 16;
        const float* r = R + t * 2048 + h * 256 + f;
        float s = 0.f;
        #pragma unroll
        for (int d = 0; d < 16; d++) s += w[d] * r[d * 16];
        float sc = isK ? (p_rel[t * 8 + h] * 0.25f) : 1.f;
        (isK ? d_tmpK : d_tmpM)[t][i * HID + o] = s * sc;
    } else if (blk < 258) {
        int idx = (blk - 256) * 256 + tid;
        int mat = idx >> 7;
        int i   = idx & 127;
        int t = mat >> 1;
        bool isK = (mat & 1) == 0;
        int st = t + 1;
        const float* W = isK ? Wk : Wv;
        const float* b = isK ? bk : bv;
        float s = b[st * HID + i];
        for (int j = 0; j < HID; j++)
            s += bpre[st * HID + j] * W[st * HID * HID + j * HID + i];
        (isK ? d_binK : d_binM)[t][i] = s;
    } else {
        int idx = (blk - 258) * 256 + tid;
        float g = 1.f / (1.f + expf(-skip[0]));
        if (idx < 1024) {
            int i = idx >> 3, c = idx & 7;
            float s = 0.f;
            for (int k = 0; k < HID; k++)
                s += Wa[i * HID + k] * Wlin[k * 8 + c];
            d_W1[idx] = g * s;
            d_W2[idx] = (1.f - g) * Wlin[idx];
        }
        if (idx < 8) {
            float s = 0.f;
            for (int k = 0; k < HID; k++)
                s += ba[k] * Wlin[k * 8 + idx];
            d_bf[idx] = g * s + blin[idx];
        }
    }
}

// ---------------- fused weight prep (phase 2): combine + compose_bias + zero ----------------
#define NB_ZERO ((NM + 255) / 256)
__global__ void k_prep2(const float* __restrict__ Wpre_d, const float* __restrict__ Wpre_a,
                        const float* __restrict__ a_rel, const float* __restrict__ m_rel,
                        const float* __restrict__ p_rel) {
    int blk = blockIdx.x;
    int tid = threadIdx.x;
    if (blk < 256) {
        int idx = blk * 256 + tid;
        int mat = idx >> 14;
        int rem = idx & 16383;
        int i = rem >> 7;
        int j = rem & 127;
        int t = mat >> 1;
        bool isK = (mat & 1) == 0;
        const float* Wpre = (t == 0) ? Wpre_d : Wpre_a;
        const float* tmp = (isK ? d_tmpK : d_tmpM)[t];
        float s = 0.f;
        for (int k = 0; k < HID; k++)
            s += Wpre[i * HID + k] * tmp[k * HID + j];
        d_WKM[t][i * 256 + (isK ? 0 : 128) + j] = s;
    } else if (blk < 258) {
        int idx = (blk - 256) * 256 + tid;
        int mat = idx >> 7;
        int o = idx & 127;
        int h = o >> 4, f = o & 15;
        int t = mat >> 1;
        bool isK = (mat & 1) == 0;
        const float* bin = (isK ? d_binK : d_binM)[t];
        const float* R = isK ? a_rel : m_rel;
        const float* r = R + t * 2048 + h * 256 + f;
        float s = 0.f;
        #pragma unroll
        for (int d = 0; d < 16; d++) s += bin[h * 16 + d] * r[d * 16];
        float sc = isK ? (p_rel[t * 8 + h] * 0.25f) : 1.f;
        d_bKM[t][(isK ? 0 : 128) + o] = s * sc;
    } else {
        // zero d_cnt and scan state
        int i = (blk - 258) * 256 + tid;
        if (i < NM) d_cnt[i] = 0;
        if (i < 128) { d_scanFlag[i] = 0; d_scanIncl[i] = 0; }
    }
}

// ---------------- bf16x3 tensor-core GEMM body, double-buffered, 1 sync/chunk ----
#define APITCH 40
#define BPITCH 136
#define AH_E 0
#define AL_E 5120
#define BH_E 10240
#define BL_E 14592
#define STAGE_E 18944
#define GEMM_SMEM (2 * STAGE_E * 2)   // bytes

__device__ __forceinline__ unsigned smem_u32p(const void* p) {
    return (unsigned)__cvta_generic_to_shared(p);
}
__device__ __forceinline__ void ldsm4(unsigned* r, unsigned addr) {
    asm volatile("ldmatrix.sync.aligned.m8n8.x4.shared.b16 {%0,%1,%2,%3}, [%4];"
        : "=r"(r[0]), "=r"(r[1]), "=r"(r[2]), "=r"(r[3]) : "r"(addr));
}
__device__ __forceinline__ void ldsm4t(unsigned* r, unsigned addr) {
    asm volatile("ldmatrix.sync.aligned.m8n8.x4.trans.shared.b16 {%0,%1,%2,%3}, [%4];"
        : "=r"(r[0]), "=r"(r[1]), "=r"(r[2]), "=r"(r[3]) : "r"(addr));
}
__device__ __forceinline__ void mma16816(float* c, const unsigned* a, const unsigned* b) {
    asm volatile("mma.sync.aligned.m16n8k16.row.col.f32.bf16.bf16.f32 "
        "{%0,%1,%2,%3}, {%4,%5,%6,%7}, {%8,%9}, {%0,%1,%2,%3};"
        : "+f"(c[0]), "+f"(c[1]), "+f"(c[2]), "+f"(c[3])
        : "r"(a[0]), "r"(a[1]), "r"(a[2]), "r"(a[3]), "r"(b[0]), "r"(b[1]));
}
__device__ __forceinline__ unsigned pack2(__nv_bfloat16 a, __nv_bfloat16 b) {
    __nv_bfloat162 t = __halves2bfloat162(a, b);
    return *reinterpret_cast<unsigned*>(&t);
}
__device__ __forceinline__ void split4(float4 v, uint2& hi, uint2& lo) {
    __nv_bfloat16 h0 = __float2bfloat16_rn(v.x);
    __nv_bfloat16 h1 = __float2bfloat16_rn(v.y);
    __nv_bfloat16 h2 = __float2bfloat16_rn(v.z);
    __nv_bfloat16 h3 = __float2bfloat16_rn(v.w);
    __nv_bfloat16 l0 = __float2bfloat16_rn(v.x - __bfloat162float(h0));
    __nv_bfloat16 l1 = __float2bfloat16_rn(v.y - __bfloat162float(h1));
    __nv_bfloat16 l2 = __float2bfloat16_rn(v.z - __bfloat162float(h2));
    __nv_bfloat16 l3 = __float2bfloat16_rn(v.w - __bfloat162float(h3));
    hi = make_uint2(pack2(h0, h1), pack2(h2, h3));
    lo = make_uint2(pack2(l0, l1), pack2(l2, l3));
}

__device__ __forceinline__ void gemm_body(
    const float* __restrict__ A, const float* __restrict__ B, int ldb,
    const float* __restrict__ bias, float* __restrict__ C, int ldc,
    int M, int K, int row0, int col0, __nv_bfloat16* sm) {
    const int tid = threadIdx.x;
    const int warp = tid >> 5;
    const int lane = tid & 31;
    const int wr0 = (warp >> 1) * 32;
    const int wn0 = (warp & 1) * 64;

    float acc[2][8][4];
    #pragma unroll
    for (int m = 0; m < 2; m++)
        #pragma unroll
        for (int j = 0; j < 8; j++)
            #pragma unroll
            for (int c = 0; c < 4; c++) acc[m][j][c] = 0.f;

    const int nc = K >> 5;
    float4 pa[4], pb[4];

    #pragma unroll
    for (int l = 0; l < 4; l++) {
        int idx = tid + l * 256;
        int row = idx >> 3, kq = (idx & 7) << 2;
        int gr = row0 + row;
        pa[l] = (gr < M) ? *reinterpret_cast<const float4*>(A + (size_t)gr * K + kq)
                         : make_float4(0.f, 0.f, 0.f, 0.f);
        int kk = idx >> 5, n = (idx & 31) << 2;
        pb[l] = *reinterpret_cast<const float4*>(B + (size_t)kk * ldb + col0 + n);
    }

    for (int c = 0; c < nc; c++) {
        __nv_bfloat16* st = sm + (c & 1) * STAGE_E;
        #pragma unroll
        for (int l = 0; l < 4; l++) {
            int idx = tid + l * 256;
            int row = idx >> 3, kq = (idx & 7) << 2;
            uint2 hi, lo;
            split4(pa[l], hi, lo);
            int offA = row * APITCH + kq;
            *reinterpret_cast<uint2*>(&st[AH_E + offA]) = hi;
            *reinterpret_cast<uint2*>(&st[AL_E + offA]) = lo;
            int kk = idx >> 5, n = (idx & 31) << 2;
            split4(pb[l], hi, lo);
            int offB = kk * BPITCH + n;
            *reinterpret_cast<uint2*>(&st[BH_E + offB]) = hi;
            *reinterpret_cast<uint2*>(&st[BL_E + offB]) = lo;
        }
        __syncthreads();

        if (c + 1 < nc) {
            int k0 = (c + 1) * 32;
            #pragma unroll
            for (int l = 0; l < 4; l++) {
                int idx = tid + l * 256;
                int row = idx >> 3, kq = (idx & 7) << 2;
                int gr = row0 + row;
                pa[l] = (gr < M) ? *reinterpret_cast<const float4*>(A + (size_t)gr * K + k0 + kq)
                                 : make_float4(0.f, 0.f, 0.f, 0.f);
                int kk = idx >> 5, n = (idx & 31) << 2;
                pb[l] = *reinterpret_cast<const float4*>(B + (size_t)(k0 + kk) * ldb + col0 + n);
            }
        }

        #pragma unroll
        for (int ks = 0; ks < 2; ks++) {
            unsigned ah[2][4], al[2][4];
            #pragma unroll
            for (int m = 0; m < 2; m++) {
                int r = wr0 + m * 16 + (lane & 15);
                int cc = ks * 16 + (lane >> 4) * 8;
                ldsm4(ah[m], smem_u32p(&st[AH_E + r * APITCH + cc]));
                ldsm4(al[m], smem_u32p(&st[AL_E + r * APITCH + cc]));
            }
            unsigned bh[8][2], bl[8][2];
            #pragma unroll
            for (int jj = 0; jj < 4; jj++) {
                int kr = ks * 16 + (lane & 15);
                int ncc = wn0 + jj * 16 + (lane >> 4) * 8;
                unsigned r4[4];
                ldsm4t(r4, smem_u32p(&st[BH_E + kr * BPITCH + ncc]));
                bh[2 * jj][0] = r4[0]; bh[2 * jj][1] = r4[1];
                bh[2 * jj + 1][0] = r4[2]; bh[2 * jj + 1][1] = r4[3];
                ldsm4t(r4, smem_u32p(&st[BL_E + kr * BPITCH + ncc]));
                bl[2 * jj][0] = r4[0]; bl[2 * jj][1] = r4[1];
                bl[2 * jj + 1][0] = r4[2]; bl[2 * jj + 1][1] = r4[3];
            }
            #pragma unroll
            for (int m = 0; m < 2; m++)
                #pragma unroll
                for (int j = 0; j < 8; j++) {
                    mma16816(acc[m][j], ah[m], bh[j]);
                    mma16816(acc[m][j], ah[m], bl[j]);
                    mma16816(acc[m][j], al[m], bh[j]);
                }
        }
    }

    #pragma unroll
    for (int m = 0; m < 2; m++) {
        int r_lo = row0 + wr0 + m * 16 + (lane >> 2);
        #pragma unroll
        for (int j = 0; j < 8; j++) {
            int col = col0 + wn0 + j * 8 + (lane & 3) * 2;
            float b0 = bias[col], b1 = bias[col + 1];
            if (r_lo < M) {
                float2 v = make_float2(acc[m][j][0] + b0, acc[m][j][1] + b1);
                *reinterpret_cast<float2*>(C + (size_t)r_lo * ldc + col) = v;
            }
            if (r_lo + 8 < M) {
                float2 v = make_float2(acc[m][j][2] + b0, acc[m][j][3] + b1);
                *reinterpret_cast<float2*>(C + (size_t)(r_lo + 8) * ldc + col) = v;
            }
        }
    }
}

// mega launch: GEMM1 (movie pre-encoder) + GEMMs 3/4 (dir/act K|M)
#define NB1 782                 // ceil(NM/128)
#define NB3 314                 // ceil(ND/128)*2
#define NB4 782                 // ceil(NA/128)*2
#define NB_MEGA (NB1 + NB3 + NB4)
__global__ __launch_bounds__(256) void k_gemm_mega(
    const float* __restrict__ x_movie, const float* __restrict__ Wpre_m,
    const float* __restrict__ bpre, float* __restrict__ xs0,
    const float* __restrict__ x_dir, const float* __restrict__ x_act,
    const float* __restrict__ WKM, const float* __restrict__ bKM,
    float* __restrict__ ktmt) {
    extern __shared__ __align__(16) __nv_bfloat16 sm[];
    int b = blockIdx.x;
    if (b < NB1) {
        gemm_body(x_movie, Wpre_m, 128, bpre, xs0, 128, NM, 256, b * 128, 0, sm);
    } else if (b < NB1 + NB3) {
        b -= NB1;
        gemm_body(x_dir, WKM, 256, bKM, ktmt, 256, ND, 128,
                  (b >> 1) * 128, (b & 1) * 128, sm);
    } else {
        b -= NB1 + NB3;
        gemm_body(x_act, WKM + HID * 256, 256, bKM + 256, ktmt + (size_t)ND * 256, 256,
                  NA, 128, (b >> 1) * 128, (b & 1) * 128, sm);
    }
}

// GEMM2: q0 = xs0 @ Wq
__global__ __launch_bounds__(256) void k_gemm_tc(
    const float* __restrict__ A, const float* __restrict__ B, int ldb,
    const float* __restrict__ bias, float* __restrict__ C, int ldc, int M, int K) {
    extern __shared__ __align__(16) __nv_bfloat16 sm[];
    gemm_body(A, B, ldb, bias, C, ldc, M, K, blockIdx.x * 128, 0, sm);
}

// ---------------- fused aggregation: dual-chain online softmax + GELU + head ----------------
__global__ __launch_bounds__(512) void k_agg(float* __restrict__ out) {
    __shared__ float sW1[32 * 33];
    __shared__ float sW2[32 * 33];
    __shared__ float sbf[8];
    for (int idx = threadIdx.x; idx < 1024; idx += 512) {
        int l = idx >> 5, j = idx & 31;
        sW1[l * 33 + j] = d_W1[idx];
        sW2[l * 33 + j] = d_W2[idx];
    }
    if (threadIdx.x < 8) sbf[threadIdx.x] = d_bf[threadIdx.x];
    __syncthreads();

    int w = (blockIdx.x * blockDim.x + threadIdx.x) >> 5;
    int lane = threadIdx.x & 31;
    if (w >= NM) return;
    float4 qv = *reinterpret_cast<const float4*>(d_q0 + (size_t)w * HID + lane * 4);
    int start = d_rowptr[w];
    int cnt = d_cnt[w];

    float mx0 = -INFINITY, mx1 = -INFINITY;
    float den0 = 0.f, den1 = 0.f;
    float c0a = 0.f, c0b = 0.f, c0c = 0.f, c0d = 0.f;
    float c1a = 0.f, c1b = 0.f, c1c = 0.f, c1d = 0.f;

    int e = 0;
    for (; e + 1 < cnt; e += 2) {
        int s0 = d_col[start + e];
        int s1 = d_col[start + e + 1];
        const float* b0 = d_ktmt + (size_t)s0 * 256;
        const float* b1 = d_ktmt + (size_t)s1 * 256;
        float4 kv0 = *reinterpret_cast<const float4*>(b0 + lane * 4);
        float4 kv1 = *reinterpret_cast<const float4*>(b1 + lane * 4);
        float4 mv0 = *reinterpret_cast<const float4*>(b0 + 128 + lane * 4);
        float4 mv1 = *reinterpret_cast<const float4*>(b1 + 128 + lane * 4);
        float p0 = qv.x * kv0.x + qv.y * kv0.y + qv.z * kv0.z + qv.w * kv0.w;
        float p1 = qv.x * kv1.x + qv.y * kv1.y + qv.z * kv1.z + qv.w * kv1.w;
        p0 += __shfl_xor_sync(0xffffffffu, p0, 1);
        p1 += __shfl_xor_sync(0xffffffffu, p1, 1);
        p0 += __shfl_xor_sync(0xffffffffu, p0, 2);
        p1 += __shfl_xor_sync(0xffffffffu, p1, 2);
        if (p0 > mx0) {
            float sc = __expf(mx0 - p0);
            den0 *= sc; c0a *= sc; c0b *= sc; c0c *= sc; c0d *= sc;
            mx0 = p0;
        }
        if (p1 > mx1) {
            float sc = __expf(mx1 - p1);
            den1 *= sc; c1a *= sc; c1b *= sc; c1c *= sc; c1d *= sc;
            mx1 = p1;
        }
        float w0 = __expf(p0 - mx0);
        float w1 = __expf(p1 - mx1);
        den0 += w0; den1 += w1;
        c0a += w0 * mv0.x; c0b += w0 * mv0.y; c0c += w0 * mv0.z; c0d += w0 * mv0.w;
        c1a += w1 * mv1.x; c1b += w1 * mv1.y; c1c += w1 * mv1.z; c1d += w1 * mv1.w;
    }
    if (e < cnt) {
        int s0 = d_col[start + e];
        const float* b0 = d_ktmt + (size_t)s0 * 256;
        float4 kv0 = *reinterpret_cast<const float4*>(b0 + lane * 4);
        float4 mv0 = *reinterpret_cast<const float4*>(b0 + 128 + lane * 4);
        float p0 = qv.x * kv0.x + qv.y * kv0.y + qv.z * kv0.z + qv.w * kv0.w;
        p0 += __shfl_xor_sync(0xffffffffu, p0, 1);
        p0 += __shfl_xor_sync(0xffffffffu, p0, 2);
        if (p0 > mx0) {
            float sc = __expf(mx0 - p0);
            den0 *= sc; c0a *= sc; c0b *= sc; c0c *= sc; c0d *= sc;
            mx0 = p0;
        }
        float w0 = __expf(p0 - mx0);
        den0 += w0;
        c0a += w0 * mv0.x; c0b += w0 * mv0.y; c0c += w0 * mv0.z; c0d += w0 * mv0.w;
    }

    float a0 = 0.f, a1 = 0.f, a2 = 0.f, a3 = 0.f, den = 0.f;
    if (cnt > 0) {
        float Mx = fmaxf(mx0, mx1);
        float f0 = __expf(mx0 - Mx);
        float f1 = (mx1 == -INFINITY) ? 0.f : __expf(mx1 - Mx);
        den = den0 * f0 + den1 * f1;
        a0 = c0a * f0 + c1a * f1;
        a1 = c0b * f0 + c1b * f1;
        a2 = c0c * f0 + c1c * f1;
        a3 = c0d * f0 + c1d * f1;
    }
    float inv = (cnt > 0) ? 1.f / den : 0.f;
    a0 *= inv; a1 *= inv; a2 *= inv; a3 *= inv;
    float g0 = a0 * normcdff(a0);
    float g1 = a1 * normcdff(a1);
    float g2 = a2 * normcdff(a2);
    float g3 = a3 * normcdff(a3);
    float4 xv = *reinterpret_cast<const float4*>(d_xs0 + (size_t)w * HID + lane * 4);
    int base1 = lane * 33;
    float o[8];
    #pragma unroll
    for (int c = 0; c < 8; c++) {
        o[c] = g0 * sW1[base1 + c]      + g1 * sW1[base1 + 8 + c]
             + g2 * sW1[base1 + 16 + c] + g3 * sW1[base1 + 24 + c]
             + xv.x * sW2[base1 + c]      + xv.y * sW2[base1 + 8 + c]
             + xv.z * sW2[base1 + 16 + c] + xv.w * sW2[base1 + 24 + c];
    }
    #pragma unroll
    for (int c = 0; c < 8; c++) {
        #pragma unroll
        for (int off = 16; off; off >>= 1)
            o[c] += __shfl_xor_sync(0xffffffffu, o[c], off);
    }
    if (lane < 8) out[(size_t)w * 8 + lane] = o[lane] + sbf[lane];
}

// ---------------- launch ----------------
extern "C" void kernel_launch(void* const* d_in, const int* in_sizes, int n_in,
                              void* d_out, int out_size) {
    const float* x_movie = (const float*)d_in[0];
    const float* x_dir   = (const float*)d_in[1];
    const float* x_act   = (const float*)d_in[2];
    const int* src_dm = (const int*)d_in[3];
    const int* dst_dm = (const int*)d_in[4];
    const int* src_am = (const int*)d_in[5];
    const int* dst_am = (const int*)d_in[6];
    const float* Wpre_m = (const float*)d_in[11];
    const float* Wpre_d = (const float*)d_in[12];
    const float* Wpre_a = (const float*)d_in[13];
    const float* bpre   = (const float*)d_in[14];
    const float* Wk     = (const float*)d_in[15];
    const float* bk     = (const float*)d_in[16];
    const float* Wq     = (const float*)d_in[17];
    const float* bq     = (const float*)d_in[18];
    const float* Wv     = (const float*)d_in[19];
    const float* bv     = (const float*)d_in[20];
    const float* a_rel  = (const float*)d_in[21];
    const float* m_rel  = (const float*)d_in[22];
    const float* p_rel  = (const float*)d_in[23];
    const float* skip   = (const float*)d_in[24];
    const float* Wa     = (const float*)d_in[25];
    const float* ba     = (const float*)d_in[26];
    const float* Wlin   = (const float*)d_in[27];
    const float* blin   = (const float*)d_in[28];
    float* out = (float*)d_out;

    cudaFuncSetAttribute(k_gemm_mega, cudaFuncAttributeMaxDynamicSharedMemorySize, GEMM_SMEM);
    cudaFuncSetAttribute(k_gemm_tc, cudaFuncAttributeMaxDynamicSharedMemorySize, GEMM_SMEM);

    void *p_xs0, *p_q0, *p_ktmt, *p_WKM, *p_bKM;
    cudaGetSymbolAddress(&p_xs0, d_xs0);
    cudaGetSymbolAddress(&p_q0, d_q0);
    cudaGetSymbolAddress(&p_ktmt, d_ktmt);
    cudaGetSymbolAddress(&p_WKM, d_WKM);
    cudaGetSymbolAddress(&p_bKM, d_bKM);
    float* xs0  = (float*)p_xs0;
    float* q0   = (float*)p_q0;
    float* ktmt = (float*)p_ktmt;
    float* WKM  = (float*)p_WKM;
    float* bKM  = (float*)p_bKM;

    // weight prep (prep2 also zeroes cnt + scan state), then mega GEMM at profiled slot 3
    k_prep1<<<262, 256>>>(bpre, Wk, bk, Wv, bv, a_rel, m_rel, p_rel,
                          Wa, ba, Wlin, blin, skip);
    k_prep2<<<258 + NB_ZERO, 256>>>(Wpre_d, Wpre_a, a_rel, m_rel, p_rel);
    k_count<<<(EE + 255) / 256, 256>>>(dst_dm, dst_am);
    k_gemm_mega<<<NB_MEGA, 256, GEMM_SMEM>>>(x_movie, Wpre_m, bpre, xs0,
                                             x_dir, x_act, WKM, bKM, ktmt);
    // single-pass scan (lookback), then fill
    k_scan<<<(NM + 1023) / 1024, 1024>>>((NM + 1023) / 1024);
    k_fill<<<(EE + 255) / 256, 256>>>(src_dm, dst_dm, src_am, dst_am);

    // GEMM2: q0 = xs0 @ Wq + bq
    k_gemm_tc<<<(NM + 127) / 128, 256, GEMM_SMEM>>>(xs0, Wq, 128, bq, q0, 128, NM, 128);

    // fused dual-chain attention aggregation + GELU + output head
    k_agg<<<(NM * 32 + 511) / 512, 512>>>(out);
}

// round 16
// speedup vs baseline: 1.2993x; 1.2993x over previous
#include <cuda_runtime.h>
#include <cuda_bf16.h>
#include <math.h>
#include <stdint.h>

#define NM 100000
#define ND 20000
#define NA 50000
#define NSRC (ND + NA)
#define NE 300000
#define EE (2 * NE)
#define HID 128

// ---------------- scratch ----------------
__device__ float d_xs0[NM * HID];
__device__ float d_q0[NM * HID];
__device__ float d_ktmt[(size_t)NSRC * 256];   // per-src: cols 0-127 = K, 128-255 = M
__device__ int   d_cnt[NM];
__device__ int   d_rowptr[NM];
__device__ int   d_cursor[NM];
__device__ int   d_col[EE];
__device__ int   d_bsum[128];
__device__ float d_binK[2][HID];
__device__ float d_binM[2][HID];
__device__ float d_tmpK[2][HID * HID];
__device__ float d_tmpM[2][HID * HID];
__device__ float d_WKM[2][HID * 256];          // merged K|M weights (fp32)
__device__ float d_bKM[2][256];
__device__ float d_W1[HID * 8];
__device__ float d_W2[HID * 8];
__device__ float d_bf[8];

// ---------------- CSR: count, two-pass scan, fill ----------------
__global__ void k_count(const int* __restrict__ dst_dm, const int* __restrict__ dst_am) {
    int i = blockIdx.x * blockDim.x + threadIdx.x;
    if (i < NE)       atomicAdd(&d_cnt[dst_dm[i]], 1);
    else if (i < EE)  atomicAdd(&d_cnt[dst_am[i - NE]], 1);
}

__global__ void k_scan1() {
    __shared__ int s[1024];
    int b = blockIdx.x, tid = threadIdx.x;
    int idx = b * 1024 + tid;
    int v = (idx < NM) ? d_cnt[idx] : 0;
    s[tid] = v;
    __syncthreads();
    #pragma unroll
    for (int off = 1; off < 1024; off <<= 1) {
        int t = (tid >= off) ? s[tid - off] : 0;
        __syncthreads();
        s[tid] += t;
        __syncthreads();
    }
    if (idx < NM) d_rowptr[idx] = s[tid] - v;
    if (tid == 1023) d_bsum[b] = s[1023];
}

__global__ void k_scan3() {
    __shared__ int off;
    int b = blockIdx.x, tid = threadIdx.x;
    if (tid == 0) {
        int s = 0;
        for (int i = 0; i < b; i++) s += d_bsum[i];
        off = s;
    }
    __syncthreads();
    int idx = b * 1024 + tid;
    if (idx < NM) {
        int r = d_rowptr[idx] + off;
        d_rowptr[idx] = r;
        d_cursor[idx] = r;
    }
}

__global__ void k_fill(const int* __restrict__ src_dm, const int* __restrict__ dst_dm,
                       const int* __restrict__ src_am, const int* __restrict__ dst_am) {
    int i = blockIdx.x * blockDim.x + threadIdx.x;
    if (i >= EE) return;
    int dst, src;
    if (i < NE) { dst = dst_dm[i]; src = src_dm[i]; }
    else        { dst = dst_am[i - NE]; src = ND + src_am[i - NE]; }
    int pos = atomicAdd(&d_cursor[dst], 1);
    d_col[pos] = src;
}

// ---------------- fused weight prep (phase 1): compose + bias_inner + head ----------------
__global__ void k_prep1(const float* __restrict__ bpre,
                        const float* __restrict__ Wk, const float* __restrict__ bk,
                        const float* __restrict__ Wv, const float* __restrict__ bv,
                        const float* __restrict__ a_rel, const float* __restrict__ m_rel,
                        const float* __restrict__ p_rel,
                        const float* __restrict__ Wa, const float* __restrict__ ba,
                        const float* __restrict__ Wlin, const float* __restrict__ blin,
                        const float* __restrict__ skip) {
    int blk = blockIdx.x;
    int tid = threadIdx.x;
    if (blk < 256) {
        int idx = blk * 256 + tid;
        int mat = idx >> 14;
        int rem = idx & 16383;
        int i = rem >> 7;
        int o = rem & 127;
        int h = o >> 4, f = o & 15;
        int t = mat >> 1;
        bool isK = (mat & 1) == 0;
        int st = t + 1;
        const float* W = isK ? Wk : Wv;
        const float* R = isK ? a_rel : m_rel;
        const float* w = W + st * HID * HID + i * HID + h * 16;
        const float* r = R + t * 2048 + h * 256 + f;
        float s = 0.f;
        #pragma unroll
        for (int d = 0; d < 16; d++) s += w[d] * r[d * 16];
        float sc = isK ? (p_rel[t * 8 + h] * 0.25f) : 1.f;
        (isK ? d_tmpK : d_tmpM)[t][i * HID + o] = s * sc;
    } else if (blk < 258) {
        int idx = (blk - 256) * 256 + tid;
        int mat = idx >> 7;
        int i   = idx & 127;
        int t = mat >> 1;
        bool isK = (mat & 1) == 0;
        int st = t + 1;
        const float* W = isK ? Wk : Wv;
        const float* b = isK ? bk : bv;
        float s = b[st * HID + i];
        for (int j = 0; j < HID; j++)
            s += bpre[st * HID + j] * W[st * HID * HID + j * HID + i];
        (isK ? d_binK : d_binM)[t][i] = s;
    } else {
        int idx = (blk - 258) * 256 + tid;
        float g = 1.f / (1.f + expf(-skip[0]));
        if (idx < 1024) {
            int i = idx >> 3, c = idx & 7;
            float s = 0.f;
            for (int k = 0; k < HID; k++)
                s += Wa[i * HID + k] * Wlin[k * 8 + c];
            d_W1[idx] = g * s;
            d_W2[idx] = (1.f - g) * Wlin[idx];
        }
        if (idx < 8) {
            float s = 0.f;
            for (int k = 0; k < HID; k++)
                s += ba[k] * Wlin[k * 8 + idx];
            d_bf[idx] = g * s + blin[idx];
        }
    }
}

// ---------------- fused weight prep (phase 2): combine + compose_bias + zero_cnt ----------------
#define NB_ZERO ((NM + 255) / 256)
__global__ void k_prep2(const float* __restrict__ Wpre_d, const float* __restrict__ Wpre_a,
                        const float* __restrict__ a_rel, const float* __restrict__ m_rel,
                        const float* __restrict__ p_rel) {
    int blk = blockIdx.x;
    int tid = threadIdx.x;
    if (blk < 256) {
        int idx = blk * 256 + tid;
        int mat = idx >> 14;
        int rem = idx & 16383;
        int i = rem >> 7;
        int j = rem & 127;
        int t = mat >> 1;
        bool isK = (mat & 1) == 0;
        const float* Wpre = (t == 0) ? Wpre_d : Wpre_a;
        const float* tmp = (isK ? d_tmpK : d_tmpM)[t];
        float s = 0.f;
        for (int k = 0; k < HID; k++)
            s += Wpre[i * HID + k] * tmp[k * HID + j];
        d_WKM[t][i * 256 + (isK ? 0 : 128) + j] = s;
    } else if (blk < 258) {
        int idx = (blk - 256) * 256 + tid;
        int mat = idx >> 7;
        int o = idx & 127;
        int h = o >> 4, f = o & 15;
        int t = mat >> 1;
        bool isK = (mat & 1) == 0;
        const float* bin = (isK ? d_binK : d_binM)[t];
        const float* R = isK ? a_rel : m_rel;
        const float* r = R + t * 2048 + h * 256 + f;
        float s = 0.f;
        #pragma unroll
        for (int d = 0; d < 16; d++) s += bin[h * 16 + d] * r[d * 16];
        float sc = isK ? (p_rel[t * 8 + h] * 0.25f) : 1.f;
        d_bKM[t][(isK ? 0 : 128) + o] = s * sc;
    } else {
        int i = (blk - 258) * 256 + tid;
        if (i < NM) d_cnt[i] = 0;
    }
}

// ---------------- bf16x3 tensor-core GEMM body, double-buffered, 1 sync/chunk ----
#define APITCH 40
#define BPITCH 136
#define AH_E 0
#define AL_E 5120
#define BH_E 10240
#define BL_E 14592
#define STAGE_E 18944
#define GEMM_SMEM (2 * STAGE_E * 2)   // bytes

__device__ __forceinline__ unsigned smem_u32p(const void* p) {
    return (unsigned)__cvta_generic_to_shared(p);
}
__device__ __forceinline__ void ldsm4(unsigned* r, unsigned addr) {
    asm volatile("ldmatrix.sync.aligned.m8n8.x4.shared.b16 {%0,%1,%2,%3}, [%4];"
        : "=r"(r[0]), "=r"(r[1]), "=r"(r[2]), "=r"(r[3]) : "r"(addr));
}
__device__ __forceinline__ void ldsm4t(unsigned* r, unsigned addr) {
    asm volatile("ldmatrix.sync.aligned.m8n8.x4.trans.shared.b16 {%0,%1,%2,%3}, [%4];"
        : "=r"(r[0]), "=r"(r[1]), "=r"(r[2]), "=r"(r[3]) : "r"(addr));
}
__device__ __forceinline__ void mma16816(float* c, const unsigned* a, const unsigned* b) {
    asm volatile("mma.sync.aligned.m16n8k16.row.col.f32.bf16.bf16.f32 "
        "{%0,%1,%2,%3}, {%4,%5,%6,%7}, {%8,%9}, {%0,%1,%2,%3};"
        : "+f"(c[0]), "+f"(c[1]), "+f"(c[2]), "+f"(c[3])
        : "r"(a[0]), "r"(a[1]), "r"(a[2]), "r"(a[3]), "r"(b[0]), "r"(b[1]));
}
__device__ __forceinline__ unsigned pack2(__nv_bfloat16 a, __nv_bfloat16 b) {
    __nv_bfloat162 t = __halves2bfloat162(a, b);
    return *reinterpret_cast<unsigned*>(&t);
}
__device__ __forceinline__ void split4(float4 v, uint2& hi, uint2& lo) {
    __nv_bfloat16 h0 = __float2bfloat16_rn(v.x);
    __nv_bfloat16 h1 = __float2bfloat16_rn(v.y);
    __nv_bfloat16 h2 = __float2bfloat16_rn(v.z);
    __nv_bfloat16 h3 = __float2bfloat16_rn(v.w);
    __nv_bfloat16 l0 = __float2bfloat16_rn(v.x - __bfloat162float(h0));
    __nv_bfloat16 l1 = __float2bfloat16_rn(v.y - __bfloat162float(h1));
    __nv_bfloat16 l2 = __float2bfloat16_rn(v.z - __bfloat162float(h2));
    __nv_bfloat16 l3 = __float2bfloat16_rn(v.w - __bfloat162float(h3));
    hi = make_uint2(pack2(h0, h1), pack2(h2, h3));
    lo = make_uint2(pack2(l0, l1), pack2(l2, l3));
}

__device__ __forceinline__ void gemm_body(
    const float* __restrict__ A, const float* __restrict__ B, int ldb,
    const float* __restrict__ bias, float* __restrict__ C, int ldc,
    int M, int K, int row0, int col0, __nv_bfloat16* sm) {
    const int tid = threadIdx.x;
    const int warp = tid >> 5;
    const int lane = tid & 31;
    const int wr0 = (warp >> 1) * 32;
    const int wn0 = (warp & 1) * 64;

    float acc[2][8][4];
    #pragma unroll
    for (int m = 0; m < 2; m++)
        #pragma unroll
        for (int j = 0; j < 8; j++)
            #pragma unroll
            for (int c = 0; c < 4; c++) acc[m][j][c] = 0.f;

    const int nc = K >> 5;
    float4 pa[4], pb[4];

    #pragma unroll
    for (int l = 0; l < 4; l++) {
        int idx = tid + l * 256;
        int row = idx >> 3, kq = (idx & 7) << 2;
        int gr = row0 + row;
        pa[l] = (gr < M) ? *reinterpret_cast<const float4*>(A + (size_t)gr * K + kq)
                         : make_float4(0.f, 0.f, 0.f, 0.f);
        int kk = idx >> 5, n = (idx & 31) << 2;
        pb[l] = *reinterpret_cast<const float4*>(B + (size_t)kk * ldb + col0 + n);
    }

    for (int c = 0; c < nc; c++) {
        __nv_bfloat16* st = sm + (c & 1) * STAGE_E;
        #pragma unroll
        for (int l = 0; l < 4; l++) {
            int idx = tid + l * 256;
            int row = idx >> 3, kq = (idx & 7) << 2;
            uint2 hi, lo;
            split4(pa[l], hi, lo);
            int offA = row * APITCH + kq;
            *reinterpret_cast<uint2*>(&st[AH_E + offA]) = hi;
            *reinterpret_cast<uint2*>(&st[AL_E + offA]) = lo;
            int kk = idx >> 5, n = (idx & 31) << 2;
            split4(pb[l], hi, lo);
            int offB = kk * BPITCH + n;
            *reinterpret_cast<uint2*>(&st[BH_E + offB]) = hi;
            *reinterpret_cast<uint2*>(&st[BL_E + offB]) = lo;
        }
        __syncthreads();          // single barrier per chunk (double buffer)

        if (c + 1 < nc) {
            int k0 = (c + 1) * 32;
            #pragma unroll
            for (int l = 0; l < 4; l++) {
                int idx = tid + l * 256;
                int row = idx >> 3, kq = (idx & 7) << 2;
                int gr = row0 + row;
                pa[l] = (gr < M) ? *reinterpret_cast<const float4*>(A + (size_t)gr * K + k0 + kq)
                                 : make_float4(0.f, 0.f, 0.f, 0.f);
                int kk = idx >> 5, n = (idx & 31) << 2;
                pb[l] = *reinterpret_cast<const float4*>(B + (size_t)(k0 + kk) * ldb + col0 + n);
            }
        }

        #pragma unroll
        for (int ks = 0; ks < 2; ks++) {
            unsigned ah[2][4], al[2][4];
            #pragma unroll
            for (int m = 0; m < 2; m++) {
                int r = wr0 + m * 16 + (lane & 15);
                int cc = ks * 16 + (lane >> 4) * 8;
                ldsm4(ah[m], smem_u32p(&st[AH_E + r * APITCH + cc]));
                ldsm4(al[m], smem_u32p(&st[AL_E + r * APITCH + cc]));
            }
            unsigned bh[8][2], bl[8][2];
            #pragma unroll
            for (int jj = 0; jj < 4; jj++) {
                int kr = ks * 16 + (lane & 15);
                int ncc = wn0 + jj * 16 + (lane >> 4) * 8;
                unsigned r4[4];
                ldsm4t(r4, smem_u32p(&st[BH_E + kr * BPITCH + ncc]));
                bh[2 * jj][0] = r4[0]; bh[2 * jj][1] = r4[1];
                bh[2 * jj + 1][0] = r4[2]; bh[2 * jj + 1][1] = r4[3];
                ldsm4t(r4, smem_u32p(&st[BL_E + kr * BPITCH + ncc]));
                bl[2 * jj][0] = r4[0]; bl[2 * jj][1] = r4[1];
                bl[2 * jj + 1][0] = r4[2]; bl[2 * jj + 1][1] = r4[3];
            }
            #pragma unroll
            for (int m = 0; m < 2; m++)
                #pragma unroll
                for (int j = 0; j < 8; j++) {
                    mma16816(acc[m][j], ah[m], bh[j]);
                    mma16816(acc[m][j], ah[m], bl[j]);
                    mma16816(acc[m][j], al[m], bh[j]);
                }
        }
    }

    #pragma unroll
    for (int m = 0; m < 2; m++) {
        int r_lo = row0 + wr0 + m * 16 + (lane >> 2);
        #pragma unroll
        for (int j = 0; j < 8; j++) {
            int col = col0 + wn0 + j * 8 + (lane & 3) * 2;
            float b0 = bias[col], b1 = bias[col + 1];
            if (r_lo < M) {
                float2 v = make_float2(acc[m][j][0] + b0, acc[m][j][1] + b1);
                *reinterpret_cast<float2*>(C + (size_t)r_lo * ldc + col) = v;
            }
            if (r_lo + 8 < M) {
                float2 v = make_float2(acc[m][j][2] + b0, acc[m][j][3] + b1);
                *reinterpret_cast<float2*>(C + (size_t)(r_lo + 8) * ldc + col) = v;
            }
        }
    }
}

// mega launch: GEMM1 (movie pre-encoder) + GEMMs 3/4 (dir/act K|M)
#define NB1 782                 // ceil(NM/128)
#define NB3 314                 // ceil(ND/128)*2
#define NB4 782                 // ceil(NA/128)*2
#define NB_MEGA (NB1 + NB3 + NB4)
__global__ __launch_bounds__(256) void k_gemm_mega(
    const float* __restrict__ x_movie, const float* __restrict__ Wpre_m,
    const float* __restrict__ bpre, float* __restrict__ xs0,
    const float* __restrict__ x_dir, const float* __restrict__ x_act,
    const float* __restrict__ WKM, const float* __restrict__ bKM,
    float* __restrict__ ktmt) {
    extern __shared__ __align__(16) __nv_bfloat16 sm[];
    int b = blockIdx.x;
    if (b < NB1) {
        gemm_body(x_movie, Wpre_m, 128, bpre, xs0, 128, NM, 256, b * 128, 0, sm);
    } else if (b < NB1 + NB3) {
        b -= NB1;
        gemm_body(x_dir, WKM, 256, bKM, ktmt, 256, ND, 128,
                  (b >> 1) * 128, (b & 1) * 128, sm);
    } else {
        b -= NB1 + NB3;
        gemm_body(x_act, WKM + HID * 256, 256, bKM + 256, ktmt + (size_t)ND * 256, 256,
                  NA, 128, (b >> 1) * 128, (b & 1) * 128, sm);
    }
}

// GEMM2: q0 = xs0 @ Wq
__global__ __launch_bounds__(256) void k_gemm_tc(
    const float* __restrict__ A, const float* __restrict__ B, int ldb,
    const float* __restrict__ bias, float* __restrict__ C, int ldc, int M, int K) {
    extern __shared__ __align__(16) __nv_bfloat16 sm[];
    gemm_body(A, B, ldb, bias, C, ldc, M, K, blockIdx.x * 128, 0, sm);
}

// ---------------- fused aggregation: dual-chain online softmax + GELU + head ----------------
__global__ __launch_bounds__(512) void k_agg(float* __restrict__ out) {
    __shared__ float sW1[32 * 33];
    __shared__ float sW2[32 * 33];
    __shared__ float sbf[8];
    for (int idx = threadIdx.x; idx < 1024; idx += 512) {
        int l = idx >> 5, j = idx & 31;
        sW1[l * 33 + j] = d_W1[idx];
        sW2[l * 33 + j] = d_W2[idx];
    }
    if (threadIdx.x < 8) sbf[threadIdx.x] = d_bf[threadIdx.x];
    __syncthreads();

    int w = (blockIdx.x * blockDim.x + threadIdx.x) >> 5;
    int lane = threadIdx.x & 31;
    if (w >= NM) return;
    float4 qv = *reinterpret_cast<const float4*>(d_q0 + (size_t)w * HID + lane * 4);
    int start = d_rowptr[w];
    int cnt = d_cnt[w];

    float mx0 = -INFINITY, mx1 = -INFINITY;
    float den0 = 0.f, den1 = 0.f;
    float c0a = 0.f, c0b = 0.f, c0c = 0.f, c0d = 0.f;
    float c1a = 0.f, c1b = 0.f, c1c = 0.f, c1d = 0.f;

    int e = 0;
    for (; e + 1 < cnt; e += 2) {
        int s0 = d_col[start + e];
        int s1 = d_col[start + e + 1];
        const float* b0 = d_ktmt + (size_t)s0 * 256;
        const float* b1 = d_ktmt + (size_t)s1 * 256;
        float4 kv0 = *reinterpret_cast<const float4*>(b0 + lane * 4);
        float4 kv1 = *reinterpret_cast<const float4*>(b1 + lane * 4);
        float4 mv0 = *reinterpret_cast<const float4*>(b0 + 128 + lane * 4);
        float4 mv1 = *reinterpret_cast<const float4*>(b1 + 128 + lane * 4);
        float p0 = qv.x * kv0.x + qv.y * kv0.y + qv.z * kv0.z + qv.w * kv0.w;
        float p1 = qv.x * kv1.x + qv.y * kv1.y + qv.z * kv1.z + qv.w * kv1.w;
        p0 += __shfl_xor_sync(0xffffffffu, p0, 1);
        p1 += __shfl_xor_sync(0xffffffffu, p1, 1);
        p0 += __shfl_xor_sync(0xffffffffu, p0, 2);
        p1 += __shfl_xor_sync(0xffffffffu, p1, 2);
        if (p0 > mx0) {
            float sc = __expf(mx0 - p0);     // first edge: __expf(-inf)=0 zeroes empty state
            den0 *= sc; c0a *= sc; c0b *= sc; c0c *= sc; c0d *= sc;
            mx0 = p0;
        }
        if (p1 > mx1) {
            float sc = __expf(mx1 - p1);
            den1 *= sc; c1a *= sc; c1b *= sc; c1c *= sc; c1d *= sc;
            mx1 = p1;
        }
        float w0 = __expf(p0 - mx0);
        float w1 = __expf(p1 - mx1);
        den0 += w0; den1 += w1;
        c0a += w0 * mv0.x; c0b += w0 * mv0.y; c0c += w0 * mv0.z; c0d += w0 * mv0.w;
        c1a += w1 * mv1.x; c1b += w1 * mv1.y; c1c += w1 * mv1.z; c1d += w1 * mv1.w;
    }
    if (e < cnt) {
        int s0 = d_col[start + e];
        const float* b0 = d_ktmt + (size_t)s0 * 256;
        float4 kv0 = *reinterpret_cast<const float4*>(b0 + lane * 4);
        float4 mv0 = *reinterpret_cast<const float4*>(b0 + 128 + lane * 4);
        float p0 = qv.x * kv0.x + qv.y * kv0.y + qv.z * kv0.z + qv.w * kv0.w;
        p0 += __shfl_xor_sync(0xffffffffu, p0, 1);
        p0 += __shfl_xor_sync(0xffffffffu, p0, 2);
        if (p0 > mx0) {
            float sc = __expf(mx0 - p0);
            den0 *= sc; c0a *= sc; c0b *= sc; c0c *= sc; c0d *= sc;
            mx0 = p0;
        }
        float w0 = __expf(p0 - mx0);
        den0 += w0;
        c0a += w0 * mv0.x; c0b += w0 * mv0.y; c0c += w0 * mv0.z; c0d += w0 * mv0.w;
    }

    float a0 = 0.f, a1 = 0.f, a2 = 0.f, a3 = 0.f, den = 0.f;
    if (cnt > 0) {
        float Mx = fmaxf(mx0, mx1);
        float f0 = __expf(mx0 - Mx);
        float f1 = (mx1 == -INFINITY) ? 0.f : __expf(mx1 - Mx);
        den = den0 * f0 + den1 * f1;
        a0 = c0a * f0 + c1a * f1;
        a1 = c0b * f0 + c1b * f1;
        a2 = c0c * f0 + c1c * f1;
        a3 = c0d * f0 + c1d * f1;
    }
    float inv = (cnt > 0) ? 1.f / den : 0.f;
    a0 *= inv; a1 *= inv; a2 *= inv; a3 *= inv;
    float g0 = a0 * normcdff(a0);
    float g1 = a1 * normcdff(a1);
    float g2 = a2 * normcdff(a2);
    float g3 = a3 * normcdff(a3);
    float4 xv = *reinterpret_cast<const float4*>(d_xs0 + (size_t)w * HID + lane * 4);
    int base1 = lane * 33;
    float o[8];
    #pragma unroll
    for (int c = 0; c < 8; c++) {
        o[c] = g0 * sW1[base1 + c]      + g1 * sW1[base1 + 8 + c]
             + g2 * sW1[base1 + 16 + c] + g3 * sW1[base1 + 24 + c]
             + xv.x * sW2[base1 + c]      + xv.y * sW2[base1 + 8 + c]
             + xv.z * sW2[base1 + 16 + c] + xv.w * sW2[base1 + 24 + c];
    }
    #pragma unroll
    for (int c = 0; c < 8; c++) {
        #pragma unroll
        for (int off = 16; off; off >>= 1)
            o[c] += __shfl_xor_sync(0xffffffffu, o[c], off);
    }
    if (lane < 8) out[(size_t)w * 8 + lane] = o[lane] + sbf[lane];
}

// ---------------- launch ----------------
extern "C" void kernel_launch(void* const* d_in, const int* in_sizes, int n_in,
                              void* d_out, int out_size) {
    const float* x_movie = (const float*)d_in[0];
    const float* x_dir   = (const float*)d_in[1];
    const float* x_act   = (const float*)d_in[2];
    const int* src_dm = (const int*)d_in[3];
    const int* dst_dm = (const int*)d_in[4];
    const int* src_am = (const int*)d_in[5];
    const int* dst_am = (const int*)d_in[6];
    const float* Wpre_m = (const float*)d_in[11];
    const float* Wpre_d = (const float*)d_in[12];
    const float* Wpre_a = (const float*)d_in[13];
    const float* bpre   = (const float*)d_in[14];
    const float* Wk     = (const float*)d_in[15];
    const float* bk     = (const float*)d_in[16];
    const float* Wq     = (const float*)d_in[17];
    const float* bq     = (const float*)d_in[18];
    const float* Wv     = (const float*)d_in[19];
    const float* bv     = (const float*)d_in[20];
    const float* a_rel  = (const float*)d_in[21];
    const float* m_rel  = (const float*)d_in[22];
    const float* p_rel  = (const float*)d_in[23];
    const float* skip   = (const float*)d_in[24];
    const float* Wa     = (const float*)d_in[25];
    const float* ba     = (const float*)d_in[26];
    const float* Wlin   = (const float*)d_in[27];
    const float* blin   = (const float*)d_in[28];
    float* out = (float*)d_out;

    cudaFuncSetAttribute(k_gemm_mega, cudaFuncAttributeMaxDynamicSharedMemorySize, GEMM_SMEM);
    cudaFuncSetAttribute(k_gemm_tc, cudaFuncAttributeMaxDynamicSharedMemorySize, GEMM_SMEM);

    void *p_xs0, *p_q0, *p_ktmt, *p_WKM, *p_bKM;
    cudaGetSymbolAddress(&p_xs0, d_xs0);
    cudaGetSymbolAddress(&p_q0, d_q0);
    cudaGetSymbolAddress(&p_ktmt, d_ktmt);
    cudaGetSymbolAddress(&p_WKM, d_WKM);
    cudaGetSymbolAddress(&p_bKM, d_bKM);
    float* xs0  = (float*)p_xs0;
    float* q0   = (float*)p_q0;
    float* ktmt = (float*)p_ktmt;
    float* WKM  = (float*)p_WKM;
    float* bKM  = (float*)p_bKM;

    // weight prep (prep2 also zeroes cnt), then mega GEMM at the profiled slot (index 3)
    k_prep1<<<262, 256>>>(bpre, Wk, bk, Wv, bv, a_rel, m_rel, p_rel,
                          Wa, ba, Wlin, blin, skip);
    k_prep2<<<258 + NB_ZERO, 256>>>(Wpre_d, Wpre_a, a_rel, m_rel, p_rel);
    k_gemm_mega<<<NB_MEGA, 256, GEMM_SMEM>>>(x_movie, Wpre_m, bpre, xs0,
                                             x_dir, x_act, WKM, bKM, ktmt);
    // CSR build (two-pass scan, validated)
    k_count<<<(EE + 255) / 256, 256>>>(dst_dm, dst_am);
    k_scan1<<<(NM + 1023) / 1024, 1024>>>();
    k_scan3<<<(NM + 1023) / 1024, 1024>>>();
    k_fill<<<(EE + 255) / 256, 256>>>(src_dm, dst_dm, src_am, dst_am);

    // GEMM2: q0 = xs0 @ Wq + bq
    k_gemm_tc<<<(NM + 127) / 128, 256, GEMM_SMEM>>>(xs0, Wq, 128, bq, q0, 128, NM, 128);

    // fused dual-chain attention aggregation + GELU + output head
    k_agg<<<(NM * 32 + 511) / 512, 512>>>(out);
}